// round 2
// baseline (speedup 1.0000x reference)
#include <cuda_runtime.h>
#include <cuda_bf16.h>
#include <cstdint>

// ---------------- problem dims (fixed by setup_inputs) ----------------
namespace cfg {
constexpr int M = 8192;     // B*S = 4*2048
constexpr int N = 4096;     // D_OUT
constexpr int K = 4096;     // D_IN
constexpr int BM = 128, BN = 128, BK = 64;
constexpr int STAGES = 3;
constexpr int NK = K / BK;
constexpr int SMEM_BYTES = STAGES * (BM * BK + BK * BN) * 2;   // 96 KB
}

// ---------------- scratch (static device arrays: allowed) ----------------
__device__ __nv_bfloat16 g_X[(size_t)cfg::M * cfg::K];   // 64 MB  x in bf16
__device__ __nv_bfloat16 g_W[(size_t)cfg::K * cfg::N];   // 32 MB  dequantized weight [K][N]
__device__ float         g_H[cfg::M * 8];                // LoRA hidden [M][8]
__device__ int           g_q_is_int32;                   // qweight encoding flag

__constant__ float c_nf4[16] = {
    -1.0f, -0.6962f, -0.5251f, -0.3949f, -0.2844f, -0.1848f, -0.0911f, 0.0f,
     0.0796f, 0.1609f, 0.2461f, 0.3379f, 0.4407f, 0.5626f, 0.723f, 1.0f};

// ---------------- small PTX helpers ----------------
__device__ __forceinline__ uint32_t smem_u32(const void* p) {
    return (uint32_t)__cvta_generic_to_shared(p);
}
__device__ __forceinline__ void cp_async16(uint32_t s, const void* g) {
    asm volatile("cp.async.cg.shared.global [%0], [%1], 16;" :: "r"(s), "l"(g));
}
__device__ __forceinline__ void cp_commit() {
    asm volatile("cp.async.commit_group;");
}
template <int W>
__device__ __forceinline__ void cp_wait() {
    asm volatile("cp.async.wait_group %0;" :: "n"(W));
}
__device__ __forceinline__ void ldsm_x4(uint32_t a[4], uint32_t addr) {
    asm volatile("ldmatrix.sync.aligned.m8n8.x4.shared.b16 {%0,%1,%2,%3}, [%4];"
                 : "=r"(a[0]), "=r"(a[1]), "=r"(a[2]), "=r"(a[3]) : "r"(addr));
}
__device__ __forceinline__ void ldsm_x2t(uint32_t b[2], uint32_t addr) {
    asm volatile("ldmatrix.sync.aligned.m8n8.x2.trans.shared.b16 {%0,%1}, [%2];"
                 : "=r"(b[0]), "=r"(b[1]) : "r"(addr));
}
__device__ __forceinline__ void mma16816(float d[4], const uint32_t a[4], const uint32_t b[2]) {
    asm volatile(
        "mma.sync.aligned.m16n8k16.row.col.f32.bf16.bf16.f32 "
        "{%0,%1,%2,%3}, {%4,%5,%6,%7}, {%8,%9}, {%0,%1,%2,%3};"
        : "+f"(d[0]), "+f"(d[1]), "+f"(d[2]), "+f"(d[3])
        : "r"(a[0]), "r"(a[1]), "r"(a[2]), "r"(a[3]), "r"(b[0]), "r"(b[1]));
}

// ---------------- 0) detect qweight encoding (int32-per-code vs packed int8) --
// For int32 codes, every word u satisfies (uint)(u+8) < 16. For packed int8
// codes (4 per word) a word passes with p~2e-4, so 256 consecutive passes
// identify int32 with certainty.
__global__ void k_detect(const unsigned* __restrict__ q) {
    __shared__ int ok;
    if (threadIdx.x == 0) ok = 1;
    __syncthreads();
    unsigned u = q[threadIdx.x];
    if ((unsigned)(u + 8u) >= 16u) atomicAnd(&ok, 0);
    __syncthreads();
    if (threadIdx.x == 0) g_q_is_int32 = ok;
}

// ---------------- 1) x fp32 -> bf16 ----------------
__global__ void k_convert_x(const float4* __restrict__ x) {
    size_t i = (size_t)blockIdx.x * blockDim.x + threadIdx.x;   // over M*K/4
    float4 v = x[i];
    __nv_bfloat162* o = reinterpret_cast<__nv_bfloat162*>(g_X);
    o[2 * i]     = __floats2bfloat162_rn(v.x, v.y);
    o[2 * i + 1] = __floats2bfloat162_rn(v.z, v.w);
}

// ---------------- 2) NF4 dequant: W[k][n] = bf16(table[q+8]) * bf16(scale[k/128][n]) ----------------
__global__ void k_dequant(const int* __restrict__ q, const float* __restrict__ scale) {
    __shared__ float tab[16];
    if (threadIdx.x < 16) tab[threadIdx.x] = c_nf4[threadIdx.x];
    __syncthreads();
    size_t i = (size_t)blockIdx.x * blockDim.x + threadIdx.x;   // over K*N/4
    size_t n4 = i % (cfg::N / 4);
    size_t k  = i / (cfg::N / 4);
    int g = (int)(k >> 7);                                      // k / 128
    float4 s4 = *reinterpret_cast<const float4*>(scale + (size_t)g * cfg::N + n4 * 4);

    int c0, c1, c2, c3;
    if (g_q_is_int32) {
        int4 w4 = reinterpret_cast<const int4*>(q)[i];          // 4 codes, one per word
        c0 = w4.x + 8; c1 = w4.y + 8; c2 = w4.z + 8; c3 = w4.w + 8;
    } else {
        int u = q[i];                                           // 4 packed int8 codes
        c0 = ((int)(signed char)( u        & 0xff)) + 8;
        c1 = ((int)(signed char)((u >>  8) & 0xff)) + 8;
        c2 = ((int)(signed char)((u >> 16) & 0xff)) + 8;
        c3 = ((int)(signed char)( u >> 24        )) + 8;
    }
    __nv_bfloat16 w0 = __hmul(__float2bfloat16(tab[c0]), __float2bfloat16(s4.x));
    __nv_bfloat16 w1 = __hmul(__float2bfloat16(tab[c1]), __float2bfloat16(s4.y));
    __nv_bfloat16 w2 = __hmul(__float2bfloat16(tab[c2]), __float2bfloat16(s4.z));
    __nv_bfloat16 w3 = __hmul(__float2bfloat16(tab[c3]), __float2bfloat16(s4.w));
    __nv_bfloat162* o = reinterpret_cast<__nv_bfloat162*>(g_W);
    o[2 * i]     = __halves2bfloat162(w0, w1);
    o[2 * i + 1] = __halves2bfloat162(w2, w3);
}

// ---------------- 3) LoRA hidden: H[m][r] = sum_k x[m][k] * lora_a[k][r]  (fp32) ----------------
__global__ void k_lora_h(const float* __restrict__ x, const float* __restrict__ la) {
    int warp = threadIdx.x >> 5, lane = threadIdx.x & 31;
    int m = blockIdx.x * 8 + warp;
    const float4* xr = reinterpret_cast<const float4*>(x + (size_t)m * cfg::K);
    float acc[8] = {0, 0, 0, 0, 0, 0, 0, 0};
    for (int c = lane; c < cfg::K / 4; c += 32) {
        float4 v = xr[c];
        const float4* a = reinterpret_cast<const float4*>(la + (size_t)c * 32);
        float4 a0 = a[0], a1 = a[1];   // row 4c
        float4 a2 = a[2], a3 = a[3];   // row 4c+1
        float4 a4 = a[4], a5 = a[5];   // row 4c+2
        float4 a6 = a[6], a7 = a[7];   // row 4c+3
        acc[0] += v.x * a0.x + v.y * a2.x + v.z * a4.x + v.w * a6.x;
        acc[1] += v.x * a0.y + v.y * a2.y + v.z * a4.y + v.w * a6.y;
        acc[2] += v.x * a0.z + v.y * a2.z + v.z * a4.z + v.w * a6.z;
        acc[3] += v.x * a0.w + v.y * a2.w + v.z * a4.w + v.w * a6.w;
        acc[4] += v.x * a1.x + v.y * a3.x + v.z * a5.x + v.w * a7.x;
        acc[5] += v.x * a1.y + v.y * a3.y + v.z * a5.y + v.w * a7.y;
        acc[6] += v.x * a1.z + v.y * a3.z + v.z * a5.z + v.w * a7.z;
        acc[7] += v.x * a1.w + v.y * a3.w + v.z * a5.w + v.w * a7.w;
    }
#pragma unroll
    for (int r = 0; r < 8; r++)
#pragma unroll
        for (int off = 16; off; off >>= 1)
            acc[r] += __shfl_xor_sync(0xffffffffu, acc[r], off);
    if (lane == 0) {
        float4* h = reinterpret_cast<float4*>(g_H + m * 8);
        h[0] = make_float4(acc[0], acc[1], acc[2], acc[3]);
        h[1] = make_float4(acc[4], acc[5], acc[6], acc[7]);
    }
}

// ---------------- 4) main GEMM: bf16 mma.sync, fused epilogue ----------------
__global__ void __launch_bounds__(256, 1) k_gemm(
    const float* __restrict__ bias,
    const float* __restrict__ lb,      // lora_b [8][N]
    float* __restrict__ out) {
    using namespace cfg;
    extern __shared__ __align__(128) char smem[];

    const int tid  = threadIdx.x;
    const int warp = tid >> 5, lane = tid & 31;
    const int wm = warp >> 2;          // 0..1  (64 rows each)
    const int wn = warp & 3;           // 0..3  (32 cols each)
    const int bm0 = blockIdx.y * BM;
    const int bn0 = blockIdx.x * BN;

    const uint32_t sA_base = smem_u32(smem);
    const uint32_t sB_base = sA_base + STAGES * BM * BK * 2;

    float acc[4][4][4];
#pragma unroll
    for (int i = 0; i < 4; i++)
#pragma unroll
        for (int j = 0; j < 4; j++)
#pragma unroll
            for (int e = 0; e < 4; e++) acc[i][j][e] = 0.0f;

    auto issue_loads = [&](int kt, int st) {
        // A tile: [BM][BK] bf16, 128B rows, SW128 swizzle
        {
            const char* gA = reinterpret_cast<const char*>(
                g_X + (size_t)bm0 * K + (size_t)kt * BK);
            uint32_t sbase = sA_base + st * (BM * BK * 2);
#pragma unroll
            for (int i = 0; i < 4; i++) {
                int c = tid + i * 256;       // 1024 chunks of 16B
                int row = c >> 3, col = c & 7;
                int b = row * 128 + col * 16;
                int sw = b ^ ((b >> 3) & 0x70);
                cp_async16(sbase + sw, gA + (size_t)row * (K * 2) + col * 16);
            }
        }
        // B tile: [BK][BN] bf16, 256B rows, XOR bits[6:4] ^= bits[10:8]
        {
            const char* gB = reinterpret_cast<const char*>(
                g_W + (size_t)(kt * BK) * N + bn0);
            uint32_t sbase = sB_base + st * (BK * BN * 2);
#pragma unroll
            for (int i = 0; i < 4; i++) {
                int c = tid + i * 256;
                int row = c >> 4, col = c & 15;
                int b = row * 256 + col * 16;
                int sw = b ^ ((b >> 4) & 0x70);
                cp_async16(sbase + sw, gB + (size_t)row * (N * 2) + col * 16);
            }
        }
    };

    issue_loads(0, 0); cp_commit();
    issue_loads(1, 1); cp_commit();

    for (int kt = 0; kt < NK; kt++) {
        const int st = kt % STAGES;
        cp_wait<1>();
        __syncthreads();
        const uint32_t aST = sA_base + st * (BM * BK * 2);
        const uint32_t bST = sB_base + st * (BK * BN * 2);
#pragma unroll
        for (int ks = 0; ks < BK / 16; ks++) {
            uint32_t afrag[4][4], bfrag[4][2];
#pragma unroll
            for (int mt = 0; mt < 4; mt++) {
                int row = wm * 64 + mt * 16 + (lane & 15);
                int b = row * 128 + ks * 32 + (lane >> 4) * 16;
                int sw = b ^ ((b >> 3) & 0x70);
                ldsm_x4(afrag[mt], aST + sw);
            }
#pragma unroll
            for (int nt = 0; nt < 4; nt++) {
                int row = ks * 16 + (lane & 15);
                int b = row * 256 + (wn * 32 + nt * 8) * 2;
                int sw = b ^ ((b >> 4) & 0x70);
                ldsm_x2t(bfrag[nt], bST + sw);
            }
#pragma unroll
            for (int mt = 0; mt < 4; mt++)
#pragma unroll
                for (int nt = 0; nt < 4; nt++)
                    mma16816(acc[mt][nt], afrag[mt], bfrag[nt]);
        }
        if (kt + 2 < NK) issue_loads(kt + 2, (kt + 2) % STAGES);
        cp_commit();
    }

    // ---- epilogue: bf16 round, bf16 bias add, fp32 + LoRA delta ----
    const int mrow = lane >> 2;          // 0..7
    const int ncol = (lane & 3) * 2;     // 0,2,4,6
#pragma unroll
    for (int mt = 0; mt < 4; mt++) {
        int m0 = bm0 + wm * 64 + mt * 16 + mrow;
        const float4* h0p = reinterpret_cast<const float4*>(g_H + m0 * 8);
        const float4* h1p = reinterpret_cast<const float4*>(g_H + (m0 + 8) * 8);
        float4 h0a = h0p[0], h0b = h0p[1];
        float4 h1a = h1p[0], h1b = h1p[1];
        float h0r[8] = {h0a.x, h0a.y, h0a.z, h0a.w, h0b.x, h0b.y, h0b.z, h0b.w};
        float h1r[8] = {h1a.x, h1a.y, h1a.z, h1a.w, h1b.x, h1b.y, h1b.z, h1b.w};
#pragma unroll
        for (int nt = 0; nt < 4; nt++) {
            int n0 = bn0 + wn * 32 + nt * 8 + ncol;
            float d00 = 0.f, d01 = 0.f, d10 = 0.f, d11 = 0.f;
#pragma unroll
            for (int r = 0; r < 8; r++) {
                float l0 = lb[r * N + n0];
                float l1 = lb[r * N + n0 + 1];
                d00 += h0r[r] * l0;  d01 += h0r[r] * l1;
                d10 += h1r[r] * l0;  d11 += h1r[r] * l1;
            }
            __nv_bfloat16 bb0 = __float2bfloat16(bias[n0]);
            __nv_bfloat16 bb1 = __float2bfloat16(bias[n0 + 1]);
            float o00 = __bfloat162float(__hadd(__float2bfloat16(acc[mt][nt][0]), bb0)) + 2.0f * d00;
            float o01 = __bfloat162float(__hadd(__float2bfloat16(acc[mt][nt][1]), bb1)) + 2.0f * d01;
            float o10 = __bfloat162float(__hadd(__float2bfloat16(acc[mt][nt][2]), bb0)) + 2.0f * d10;
            float o11 = __bfloat162float(__hadd(__float2bfloat16(acc[mt][nt][3]), bb1)) + 2.0f * d11;
            *reinterpret_cast<float2*>(out + (size_t)m0 * N + n0)       = make_float2(o00, o01);
            *reinterpret_cast<float2*>(out + (size_t)(m0 + 8) * N + n0) = make_float2(o10, o11);
        }
    }
}

// ---------------- launch ----------------
extern "C" void kernel_launch(void* const* d_in, const int* in_sizes, int n_in,
                              void* d_out, int out_size) {
    using namespace cfg;
    // Bind inputs by element count (robust to metadata ordering).
    const float* x = nullptr; const void* q = nullptr; const float* scale = nullptr;
    const float* bias = nullptr; const float* la = nullptr; const float* lb = nullptr;
    for (int i = 0; i < n_in; i++) {
        switch (in_sizes[i]) {
            case 33554432: x = (const float*)d_in[i]; break;        // 8192*4096
            case 16777216: q = d_in[i]; break;                      // 4096*4096
            case 135168:   scale = (const float*)d_in[i]; break;    // 33*4096
            case 4096:     bias = (const float*)d_in[i]; break;
            case 32768:                                             // lora_a then lora_b
                if (!la) la = (const float*)d_in[i];
                else     lb = (const float*)d_in[i];
                break;
            default: break;
        }
    }
    float* out = (float*)d_out;

    k_detect<<<1, 256>>>((const unsigned*)q);
    k_convert_x<<<(int)(((size_t)M * K / 4) / 256), 256>>>((const float4*)x);
    k_dequant  <<<(int)(((size_t)K * N / 4) / 256), 256>>>((const int*)q, scale);
    k_lora_h   <<<M / 8, 256>>>(x, la);

    cudaFuncSetAttribute(k_gemm, cudaFuncAttributeMaxDynamicSharedMemorySize, SMEM_BYTES);
    k_gemm<<<dim3(N / BN, M / BM), 256, SMEM_BYTES>>>(bias, lb, out);
}

// round 3
// speedup vs baseline: 1.2301x; 1.2301x over previous
#include <cuda_runtime.h>
#include <cuda_bf16.h>
#include <cstdint>

// ---------------- problem dims (fixed by setup_inputs) ----------------
namespace cfg {
constexpr int M = 8192;     // B*S = 4*2048
constexpr int N = 4096;     // D_OUT
constexpr int K = 4096;     // D_IN
constexpr int BM = 128, BN = 128, BK = 64;
constexpr int STAGES = 3;
constexpr int NK = K / BK;
constexpr int SMEM_BYTES = STAGES * (BM * BK + BK * BN) * 2;   // 96 KB
}

// ---------------- scratch (static device arrays: allowed) ----------------
__device__ __nv_bfloat16 g_X[(size_t)cfg::M * cfg::K];   // 64 MB  x in bf16
__device__ __nv_bfloat16 g_W[(size_t)cfg::K * cfg::N];   // 32 MB  dequantized weight [K][N]
__device__ float         g_H[cfg::M * 8];                // LoRA hidden [M][8]
__device__ int           g_q_is_int32;                   // qweight encoding flag

__constant__ float c_nf4[16] = {
    -1.0f, -0.6962f, -0.5251f, -0.3949f, -0.2844f, -0.1848f, -0.0911f, 0.0f,
     0.0796f, 0.1609f, 0.2461f, 0.3379f, 0.4407f, 0.5626f, 0.723f, 1.0f};

// ---------------- small PTX helpers ----------------
__device__ __forceinline__ uint32_t smem_u32(const void* p) {
    return (uint32_t)__cvta_generic_to_shared(p);
}
__device__ __forceinline__ void cp_async16(uint32_t s, const void* g) {
    asm volatile("cp.async.cg.shared.global [%0], [%1], 16;" :: "r"(s), "l"(g));
}
__device__ __forceinline__ void cp_commit() {
    asm volatile("cp.async.commit_group;");
}
template <int W>
__device__ __forceinline__ void cp_wait() {
    asm volatile("cp.async.wait_group %0;" :: "n"(W));
}
__device__ __forceinline__ void ldsm_x4(uint32_t a[4], uint32_t addr) {
    asm volatile("ldmatrix.sync.aligned.m8n8.x4.shared.b16 {%0,%1,%2,%3}, [%4];"
                 : "=r"(a[0]), "=r"(a[1]), "=r"(a[2]), "=r"(a[3]) : "r"(addr));
}
__device__ __forceinline__ void ldsm_x4t(uint32_t* b, uint32_t addr) {
    asm volatile("ldmatrix.sync.aligned.m8n8.x4.trans.shared.b16 {%0,%1,%2,%3}, [%4];"
                 : "=r"(b[0]), "=r"(b[1]), "=r"(b[2]), "=r"(b[3]) : "r"(addr));
}
__device__ __forceinline__ void mma16816(float d[4], const uint32_t a[4], const uint32_t b[2]) {
    asm volatile(
        "mma.sync.aligned.m16n8k16.row.col.f32.bf16.bf16.f32 "
        "{%0,%1,%2,%3}, {%4,%5,%6,%7}, {%8,%9}, {%0,%1,%2,%3};"
        : "+f"(d[0]), "+f"(d[1]), "+f"(d[2]), "+f"(d[3])
        : "r"(a[0]), "r"(a[1]), "r"(a[2]), "r"(a[3]), "r"(b[0]), "r"(b[1]));
}

// ---------------- 0) detect qweight encoding (int32-per-code vs packed int8) --
__global__ void k_detect(const unsigned* __restrict__ q) {
    __shared__ int ok;
    if (threadIdx.x == 0) ok = 1;
    __syncthreads();
    unsigned u = q[threadIdx.x];
    if ((unsigned)(u + 8u) >= 16u) atomicAnd(&ok, 0);
    __syncthreads();
    if (threadIdx.x == 0) g_q_is_int32 = ok;
}

// ---------------- 1) fused: LoRA hidden H = x @ lora_a  AND  x -> bf16 -------
// Block = 128 threads (4 warps). Each warp owns 8 rows; lane covers 2 k's per
// iteration, so each lora_a load (64B) is amortized across 8 rows (128 FMA).
__global__ void __launch_bounds__(128) k_lora_conv(
    const float* __restrict__ x, const float* __restrict__ la) {
    using namespace cfg;
    const int warp = threadIdx.x >> 5, lane = threadIdx.x & 31;
    const int m0 = blockIdx.x * 32 + warp * 8;
    float acc[8][8];
#pragma unroll
    for (int i = 0; i < 8; i++)
#pragma unroll
        for (int j = 0; j < 8; j++) acc[i][j] = 0.0f;

    for (int it = 0; it < K / 64; it++) {
        const int k = it * 64 + lane * 2;
        float4 a0 = *reinterpret_cast<const float4*>(la + (size_t)k * 8);
        float4 a1 = *reinterpret_cast<const float4*>(la + (size_t)k * 8 + 4);
        float4 a2 = *reinterpret_cast<const float4*>(la + (size_t)(k + 1) * 8);
        float4 a3 = *reinterpret_cast<const float4*>(la + (size_t)(k + 1) * 8 + 4);
#pragma unroll
        for (int rr = 0; rr < 8; rr++) {
            const size_t off = (size_t)(m0 + rr) * K + k;
            float2 xv = *reinterpret_cast<const float2*>(x + off);
            *reinterpret_cast<__nv_bfloat162*>(g_X + off) =
                __floats2bfloat162_rn(xv.x, xv.y);
            acc[rr][0] += xv.x * a0.x + xv.y * a2.x;
            acc[rr][1] += xv.x * a0.y + xv.y * a2.y;
            acc[rr][2] += xv.x * a0.z + xv.y * a2.z;
            acc[rr][3] += xv.x * a0.w + xv.y * a2.w;
            acc[rr][4] += xv.x * a1.x + xv.y * a3.x;
            acc[rr][5] += xv.x * a1.y + xv.y * a3.y;
            acc[rr][6] += xv.x * a1.z + xv.y * a3.z;
            acc[rr][7] += xv.x * a1.w + xv.y * a3.w;
        }
    }
#pragma unroll
    for (int rr = 0; rr < 8; rr++)
#pragma unroll
        for (int r = 0; r < 8; r++) {
            float v = acc[rr][r];
#pragma unroll
            for (int off = 16; off; off >>= 1)
                v += __shfl_xor_sync(0xffffffffu, v, off);
            if (lane == 0) g_H[(m0 + rr) * 8 + r] = v;
        }
}

// ---------------- 2) NF4 dequant: W[k][n] = bf16(table[q+8]) * bf16(scale[k/128][n]) ----------------
__global__ void k_dequant(const int* __restrict__ q, const float* __restrict__ scale) {
    __shared__ float tab[16];
    if (threadIdx.x < 16) tab[threadIdx.x] = c_nf4[threadIdx.x];
    __syncthreads();
    size_t i = (size_t)blockIdx.x * blockDim.x + threadIdx.x;   // over K*N/4
    size_t n4 = i % (cfg::N / 4);
    size_t k  = i / (cfg::N / 4);
    int g = (int)(k >> 7);                                      // k / 128
    float4 s4 = *reinterpret_cast<const float4*>(scale + (size_t)g * cfg::N + n4 * 4);

    int c0, c1, c2, c3;
    if (g_q_is_int32) {
        int4 w4 = reinterpret_cast<const int4*>(q)[i];          // 4 codes, one per word
        c0 = w4.x + 8; c1 = w4.y + 8; c2 = w4.z + 8; c3 = w4.w + 8;
    } else {
        int u = q[i];                                           // 4 packed int8 codes
        c0 = ((int)(signed char)( u        & 0xff)) + 8;
        c1 = ((int)(signed char)((u >>  8) & 0xff)) + 8;
        c2 = ((int)(signed char)((u >> 16) & 0xff)) + 8;
        c3 = ((int)(signed char)( u >> 24        )) + 8;
    }
    __nv_bfloat16 w0 = __hmul(__float2bfloat16(tab[c0]), __float2bfloat16(s4.x));
    __nv_bfloat16 w1 = __hmul(__float2bfloat16(tab[c1]), __float2bfloat16(s4.y));
    __nv_bfloat16 w2 = __hmul(__float2bfloat16(tab[c2]), __float2bfloat16(s4.z));
    __nv_bfloat16 w3 = __hmul(__float2bfloat16(tab[c3]), __float2bfloat16(s4.w));
    __nv_bfloat162* o = reinterpret_cast<__nv_bfloat162*>(g_W);
    o[2 * i]     = __halves2bfloat162(w0, w1);
    o[2 * i + 1] = __halves2bfloat162(w2, w3);
}

// ---------------- 3) main GEMM: bf16 mma.sync, fused epilogue ----------------
__global__ void __launch_bounds__(256, 1) k_gemm(
    const float* __restrict__ bias,
    const float* __restrict__ lb,      // lora_b [8][N]
    float* __restrict__ out) {
    using namespace cfg;
    extern __shared__ __align__(128) char smem[];

    const int tid  = threadIdx.x;
    const int warp = tid >> 5, lane = tid & 31;
    const int wm = warp >> 2;          // 0..1  (64 rows each)
    const int wn = warp & 3;           // 0..3  (32 cols each)
    const int bm0 = blockIdx.y * BM;
    const int bn0 = blockIdx.x * BN;

    const uint32_t sA_base = smem_u32(smem);
    const uint32_t sB_base = sA_base + STAGES * BM * BK * 2;

    float acc[4][4][4];
#pragma unroll
    for (int i = 0; i < 4; i++)
#pragma unroll
        for (int j = 0; j < 4; j++)
#pragma unroll
            for (int e = 0; e < 4; e++) acc[i][j][e] = 0.0f;

    auto issue_loads = [&](int kt, int st) {
        // A tile: [BM][BK] bf16, 128B rows, SW128 swizzle
        {
            const char* gA = reinterpret_cast<const char*>(
                g_X + (size_t)bm0 * K + (size_t)kt * BK);
            uint32_t sbase = sA_base + st * (BM * BK * 2);
#pragma unroll
            for (int i = 0; i < 4; i++) {
                int c = tid + i * 256;       // 1024 chunks of 16B
                int row = c >> 3, col = c & 7;
                int b = row * 128 + col * 16;
                int sw = b ^ ((b >> 3) & 0x70);
                cp_async16(sbase + sw, gA + (size_t)row * (K * 2) + col * 16);
            }
        }
        // B tile: [BK][BN] bf16, 256B rows, XOR bits[6:4] ^= bits[10:8]
        {
            const char* gB = reinterpret_cast<const char*>(
                g_W + (size_t)(kt * BK) * N + bn0);
            uint32_t sbase = sB_base + st * (BK * BN * 2);
#pragma unroll
            for (int i = 0; i < 4; i++) {
                int c = tid + i * 256;
                int row = c >> 4, col = c & 15;
                int b = row * 256 + col * 16;
                int sw = b ^ ((b >> 4) & 0x70);
                cp_async16(sbase + sw, gB + (size_t)row * (N * 2) + col * 16);
            }
        }
    };

    issue_loads(0, 0); cp_commit();
    issue_loads(1, 1); cp_commit();

    for (int kt = 0; kt < NK; kt++) {
        const int st = kt % STAGES;
        cp_wait<1>();
        __syncthreads();
        // Prefetch kt+2 FIRST so the DMA overlaps the mma block below.
        if (kt + 2 < NK) issue_loads(kt + 2, (kt + 2) % STAGES);
        cp_commit();

        const uint32_t aST = sA_base + st * (BM * BK * 2);
        const uint32_t bST = sB_base + st * (BK * BN * 2);
#pragma unroll
        for (int ks = 0; ks < BK / 16; ks++) {
            uint32_t afrag[4][4], bfrag[8];
#pragma unroll
            for (int mt = 0; mt < 4; mt++) {
                int row = wm * 64 + mt * 16 + (lane & 15);
                int b = row * 128 + ks * 32 + (lane >> 4) * 16;
                int sw = b ^ ((b >> 3) & 0x70);
                ldsm_x4(afrag[mt], aST + sw);
            }
#pragma unroll
            for (int nt2 = 0; nt2 < 2; nt2++) {
                int mat = lane >> 3, r = lane & 7;
                int row = ks * 16 + (mat & 1) * 8 + r;
                int colb = (wn * 32 + nt2 * 16 + (mat >> 1) * 8) * 2;
                int b = row * 256 + colb;
                int sw = b ^ ((b >> 4) & 0x70);
                ldsm_x4t(&bfrag[nt2 * 4], bST + sw);
            }
#pragma unroll
            for (int mt = 0; mt < 4; mt++)
#pragma unroll
                for (int nb = 0; nb < 4; nb++)
                    mma16816(acc[mt][nb], afrag[mt], &bfrag[nb * 2]);
        }
    }

    // ---- epilogue: bf16 round, bf16 bias add, fp32 + LoRA delta ----
    const int mrow = lane >> 2;          // 0..7
    const int ncol = (lane & 3) * 2;     // 0,2,4,6
#pragma unroll
    for (int mt = 0; mt < 4; mt++) {
        int m0 = bm0 + wm * 64 + mt * 16 + mrow;
        const float4* h0p = reinterpret_cast<const float4*>(g_H + m0 * 8);
        const float4* h1p = reinterpret_cast<const float4*>(g_H + (m0 + 8) * 8);
        float4 h0a = h0p[0], h0b = h0p[1];
        float4 h1a = h1p[0], h1b = h1p[1];
        float h0r[8] = {h0a.x, h0a.y, h0a.z, h0a.w, h0b.x, h0b.y, h0b.z, h0b.w};
        float h1r[8] = {h1a.x, h1a.y, h1a.z, h1a.w, h1b.x, h1b.y, h1b.z, h1b.w};
#pragma unroll
        for (int nt = 0; nt < 4; nt++) {
            int n0 = bn0 + wn * 32 + nt * 8 + ncol;
            float d00 = 0.f, d01 = 0.f, d10 = 0.f, d11 = 0.f;
#pragma unroll
            for (int r = 0; r < 8; r++) {
                float l0 = lb[r * N + n0];
                float l1 = lb[r * N + n0 + 1];
                d00 += h0r[r] * l0;  d01 += h0r[r] * l1;
                d10 += h1r[r] * l0;  d11 += h1r[r] * l1;
            }
            __nv_bfloat16 bb0 = __float2bfloat16(bias[n0]);
            __nv_bfloat16 bb1 = __float2bfloat16(bias[n0 + 1]);
            float o00 = __bfloat162float(__hadd(__float2bfloat16(acc[mt][nt][0]), bb0)) + 2.0f * d00;
            float o01 = __bfloat162float(__hadd(__float2bfloat16(acc[mt][nt][1]), bb1)) + 2.0f * d01;
            float o10 = __bfloat162float(__hadd(__float2bfloat16(acc[mt][nt][2]), bb0)) + 2.0f * d10;
            float o11 = __bfloat162float(__hadd(__float2bfloat16(acc[mt][nt][3]), bb1)) + 2.0f * d11;
            *reinterpret_cast<float2*>(out + (size_t)m0 * N + n0)       = make_float2(o00, o01);
            *reinterpret_cast<float2*>(out + (size_t)(m0 + 8) * N + n0) = make_float2(o10, o11);
        }
    }
}

// ---------------- launch ----------------
extern "C" void kernel_launch(void* const* d_in, const int* in_sizes, int n_in,
                              void* d_out, int out_size) {
    using namespace cfg;
    // Bind inputs by element count (robust to metadata ordering).
    const float* x = nullptr; const void* q = nullptr; const float* scale = nullptr;
    const float* bias = nullptr; const float* la = nullptr; const float* lb = nullptr;
    for (int i = 0; i < n_in; i++) {
        switch (in_sizes[i]) {
            case 33554432: x = (const float*)d_in[i]; break;        // 8192*4096
            case 16777216: q = d_in[i]; break;                      // 4096*4096
            case 135168:   scale = (const float*)d_in[i]; break;    // 33*4096
            case 4096:     bias = (const float*)d_in[i]; break;
            case 32768:                                             // lora_a then lora_b
                if (!la) la = (const float*)d_in[i];
                else     lb = (const float*)d_in[i];
                break;
            default: break;
        }
    }
    float* out = (float*)d_out;

    k_detect<<<1, 256>>>((const unsigned*)q);
    k_dequant<<<(int)(((size_t)K * N / 4) / 256), 256>>>((const int*)q, scale);
    k_lora_conv<<<M / 32, 128>>>(x, la);

    cudaFuncSetAttribute(k_gemm, cudaFuncAttributeMaxDynamicSharedMemorySize, SMEM_BYTES);
    k_gemm<<<dim3(N / BN, M / BM), 256, SMEM_BYTES>>>(bias, lb, out);
}

// round 5
// speedup vs baseline: 2.7404x; 2.2277x over previous
#include <cuda_runtime.h>
#include <cuda_bf16.h>
#include <cstdint>

// Arch-feature gate: tcgen05 only exists in sm_103a-family passes. In the
// compute_103 (PTX) pass this is 0 and we compile an mma.sync mainloop.
#if defined(__CUDA_ARCH__) && defined(__CUDA_ARCH_HAS_FEATURE__)
#if __CUDA_ARCH_HAS_FEATURE__(SM103_ALL)
#define HAS_TC 1
#else
#define HAS_TC 0
#endif
#else
#define HAS_TC 0
#endif

// ---------------- problem dims (fixed by setup_inputs) ----------------
namespace cfg {
constexpr int M = 8192;     // B*S
constexpr int N = 4096;     // D_OUT
constexpr int K = 4096;     // D_IN
constexpr int BM = 128, BN = 256, BK = 64;
constexpr int STAGES = 4;
constexpr int NK = K / BK;                       // 64
constexpr int A_STAGE = BM * BK * 2;             // 16384
constexpr int B_STAGE = BN * BK * 2;             // 32768
constexpr int SMEM_A_OFF = 1024;
constexpr int SMEM_B_OFF = SMEM_A_OFF + STAGES * A_STAGE;
constexpr int SMEM_TOTAL = SMEM_B_OFF + STAGES * B_STAGE;   // 197632
constexpr int MBAR_OFF = 64;
// tcgen05 idesc: dtype F32(bit4), atype BF16(bit7), btype BF16(bit10), N/8<<17, M/16<<24
constexpr uint32_t IDESC = 0x10u | 0x80u | 0x400u | ((BN / 8) << 17) | ((BM / 16) << 24);
}

// ---------------- scratch ----------------
__device__ __nv_bfloat16 g_X [(size_t)cfg::M * cfg::K];   // x in bf16, [M][K]
__device__ __nv_bfloat16 g_Wt[(size_t)cfg::N * cfg::K];   // W^T bf16, [N][K] K-major
__device__ float         g_H [cfg::M * 8];                // LoRA hidden
__device__ int           g_q_is_int32;

__constant__ float c_nf4[16] = {
    -1.0f, -0.6962f, -0.5251f, -0.3949f, -0.2844f, -0.1848f, -0.0911f, 0.0f,
     0.0796f, 0.1609f, 0.2461f, 0.3379f, 0.4407f, 0.5626f, 0.723f, 1.0f};

// ---------------- generic helpers ----------------
__device__ __forceinline__ uint32_t smem_u32(const void* p) {
    return (uint32_t)__cvta_generic_to_shared(p);
}
__device__ __forceinline__ void cp_async16(uint32_t s, const void* g) {
    asm volatile("cp.async.cg.shared.global [%0], [%1], 16;" :: "r"(s), "l"(g));
}
__device__ __forceinline__ void cp_commit() { asm volatile("cp.async.commit_group;"); }
template <int W>
__device__ __forceinline__ void cp_wait() {
    asm volatile("cp.async.wait_group %0;" :: "n"(W));
}
__device__ __forceinline__ uint32_t sw128(uint32_t b) { return b ^ ((b >> 3) & 0x70); }

__device__ __forceinline__ void ldsm_x4(uint32_t a[4], uint32_t addr) {
    asm volatile("ldmatrix.sync.aligned.m8n8.x4.shared.b16 {%0,%1,%2,%3}, [%4];"
                 : "=r"(a[0]), "=r"(a[1]), "=r"(a[2]), "=r"(a[3]) : "r"(addr));
}
__device__ __forceinline__ void mma16816(float d[4], const uint32_t a[4],
                                         uint32_t b0, uint32_t b1) {
    asm volatile(
        "mma.sync.aligned.m16n8k16.row.col.f32.bf16.bf16.f32 "
        "{%0,%1,%2,%3}, {%4,%5,%6,%7}, {%8,%9}, {%0,%1,%2,%3};"
        : "+f"(d[0]), "+f"(d[1]), "+f"(d[2]), "+f"(d[3])
        : "r"(a[0]), "r"(a[1]), "r"(a[2]), "r"(a[3]), "r"(b0), "r"(b1));
}

#if HAS_TC
// ---------------- tcgen05-only helpers (sm_103a pass only) ----------------
__device__ __forceinline__ uint32_t elect_one() {
    uint32_t pred;
    asm volatile("{\n\t.reg .pred p;\n\telect.sync _|p, 0xFFFFFFFF;\n\t"
                 "selp.b32 %0, 1, 0, p;\n\t}" : "=r"(pred));
    return pred;
}
__device__ __forceinline__ uint64_t make_desc(uint32_t addr) {
    constexpr uint64_t BASE =
        (uint64_t(2) << 61) | (uint64_t(1) << 46) | (uint64_t(64) << 32) | (uint64_t(1) << 16);
    return BASE | ((uint64_t)(addr >> 4) & 0x3FFF);
}
__device__ __forceinline__ void mma_f16_ss(uint32_t d, uint64_t a, uint64_t b,
                                           uint32_t idesc, uint32_t en) {
    asm volatile(
        "{\n\t.reg .pred p;\n\tsetp.ne.u32 p, %5, 0;\n\t"
        "tcgen05.mma.cta_group::1.kind::f16 [%0], %1, %2, %3, {%4, %4, %4, %4}, p;\n\t}"
        :: "r"(d), "l"(a), "l"(b), "r"(idesc), "r"(0u), "r"(en) : "memory");
}
__device__ __forceinline__ void tc_commit(uint32_t mbar) {
    asm volatile(
        "tcgen05.commit.cta_group::1.mbarrier::arrive::one.shared::cluster.b64 [%0];"
        :: "r"(mbar) : "memory");
}
__device__ __forceinline__ void mbar_init(uint32_t mbar, uint32_t cnt) {
    asm volatile("mbarrier.init.shared.b64 [%0], %1;" :: "r"(mbar), "r"(cnt) : "memory");
}
__device__ __forceinline__ void mbar_wait(uint32_t mbar, uint32_t parity) {
    uint32_t done;
    asm volatile(
        "{\n\t.reg .pred p;\n\t"
        "mbarrier.try_wait.parity.acquire.cta.shared::cta.b64 p, [%1], %2;\n\t"
        "selp.b32 %0, 1, 0, p;\n\t}"
        : "=r"(done) : "r"(mbar), "r"(parity) : "memory");
    if (!done) {
        asm volatile(
            "{\n\t.reg .pred P1;\n\t"
            "WAIT_LOOP_%=:\n\t"
            "mbarrier.try_wait.parity.acquire.cta.shared::cta.b64 P1, [%0], %1, 0x989680;\n\t"
            "@P1 bra.uni WAIT_DONE_%=;\n\t"
            "bra.uni WAIT_LOOP_%=;\n\t"
            "WAIT_DONE_%=:\n\t}"
            :: "r"(mbar), "r"(parity) : "memory");
    }
}
__device__ __forceinline__ void fence_proxy_async_cta() {
    asm volatile("fence.proxy.async.shared::cta;" ::: "memory");
}
__device__ __forceinline__ void tc_fence_after() {
    asm volatile("tcgen05.fence::after_thread_sync;" ::: "memory");
}
__device__ __forceinline__ void tc_fence_before() {
    asm volatile("tcgen05.fence::before_thread_sync;" ::: "memory");
}
__device__ __forceinline__ void tc_wait_ld() {
    asm volatile("tcgen05.wait::ld.sync.aligned;" ::: "memory");
}
__device__ __forceinline__ void ldtm_x32(uint32_t* r, uint32_t tmem_addr) {
    asm volatile(
        "tcgen05.ld.sync.aligned.32x32b.x32.b32 "
        "{%0, %1, %2, %3, %4, %5, %6, %7, "
        " %8, %9, %10, %11, %12, %13, %14, %15, "
        " %16, %17, %18, %19, %20, %21, %22, %23, "
        " %24, %25, %26, %27, %28, %29, %30, %31}, [%32];"
        : "=r"(r[0]),  "=r"(r[1]),  "=r"(r[2]),  "=r"(r[3]),
          "=r"(r[4]),  "=r"(r[5]),  "=r"(r[6]),  "=r"(r[7]),
          "=r"(r[8]),  "=r"(r[9]),  "=r"(r[10]), "=r"(r[11]),
          "=r"(r[12]), "=r"(r[13]), "=r"(r[14]), "=r"(r[15]),
          "=r"(r[16]), "=r"(r[17]), "=r"(r[18]), "=r"(r[19]),
          "=r"(r[20]), "=r"(r[21]), "=r"(r[22]), "=r"(r[23]),
          "=r"(r[24]), "=r"(r[25]), "=r"(r[26]), "=r"(r[27]),
          "=r"(r[28]), "=r"(r[29]), "=r"(r[30]), "=r"(r[31])
        : "r"(tmem_addr));
}
#endif  // HAS_TC

// ---------------- 0) detect qweight encoding ----------------
__global__ void k_detect(const unsigned* __restrict__ q) {
    __shared__ int ok;
    if (threadIdx.x == 0) ok = 1;
    __syncthreads();
    unsigned u = q[threadIdx.x];
    if ((unsigned)(u + 8u) >= 16u) atomicAnd(&ok, 0);
    __syncthreads();
    if (threadIdx.x == 0) g_q_is_int32 = ok;
}

// ---------------- 1) fused: LoRA hidden H = x @ lora_a  AND  x -> bf16 -------
__global__ void __launch_bounds__(128) k_lora_conv(
    const float* __restrict__ x, const float* __restrict__ la) {
    using namespace cfg;
    const int warp = threadIdx.x >> 5, lane = threadIdx.x & 31;
    const int m0 = blockIdx.x * 32 + warp * 8;
    float acc[8][8];
#pragma unroll
    for (int i = 0; i < 8; i++)
#pragma unroll
        for (int j = 0; j < 8; j++) acc[i][j] = 0.0f;

    for (int it = 0; it < K / 64; it++) {
        const int k = it * 64 + lane * 2;
        float4 a0 = *reinterpret_cast<const float4*>(la + (size_t)k * 8);
        float4 a1 = *reinterpret_cast<const float4*>(la + (size_t)k * 8 + 4);
        float4 a2 = *reinterpret_cast<const float4*>(la + (size_t)(k + 1) * 8);
        float4 a3 = *reinterpret_cast<const float4*>(la + (size_t)(k + 1) * 8 + 4);
#pragma unroll
        for (int rr = 0; rr < 8; rr++) {
            const size_t off = (size_t)(m0 + rr) * K + k;
            float2 xv = *reinterpret_cast<const float2*>(x + off);
            *reinterpret_cast<__nv_bfloat162*>(g_X + off) =
                __floats2bfloat162_rn(xv.x, xv.y);
            acc[rr][0] += xv.x * a0.x + xv.y * a2.x;
            acc[rr][1] += xv.x * a0.y + xv.y * a2.y;
            acc[rr][2] += xv.x * a0.z + xv.y * a2.z;
            acc[rr][3] += xv.x * a0.w + xv.y * a2.w;
            acc[rr][4] += xv.x * a1.x + xv.y * a3.x;
            acc[rr][5] += xv.x * a1.y + xv.y * a3.y;
            acc[rr][6] += xv.x * a1.z + xv.y * a3.z;
            acc[rr][7] += xv.x * a1.w + xv.y * a3.w;
        }
    }
#pragma unroll
    for (int rr = 0; rr < 8; rr++)
#pragma unroll
        for (int r = 0; r < 8; r++) {
            float v = acc[rr][r];
#pragma unroll
            for (int off = 16; off; off >>= 1)
                v += __shfl_xor_sync(0xffffffffu, v, off);
            if (lane == 0) g_H[(m0 + rr) * 8 + r] = v;
        }
}

// ---------------- 2) NF4 dequant + transpose: g_Wt[n][k] ----------------
__global__ void __launch_bounds__(256) k_dequant_t(
    const int* __restrict__ q, const float* __restrict__ scale) {
    using namespace cfg;
    __shared__ __nv_bfloat16 t[64][72];
    const int k0 = blockIdx.y * 64;
    const int n0 = blockIdx.x * 64;
    const int tid = threadIdx.x;
    const bool is32 = (g_q_is_int32 != 0);

    for (int idx = tid; idx < 64 * 64; idx += 256) {
        int kk = idx >> 6, nn = idx & 63;
        int code;
        if (is32) {
            code = q[(size_t)(k0 + kk) * N + n0 + nn] + 8;
        } else {
            code = (int)((const signed char*)q)[(size_t)(k0 + kk) * N + n0 + nn] + 8;
        }
        float s = scale[(size_t)((k0 + kk) >> 7) * N + n0 + nn];
        t[kk][nn] = __hmul(__float2bfloat16(c_nf4[code]), __float2bfloat16(s));
    }
    __syncthreads();
    for (int idx = tid; idx < 64 * 32; idx += 256) {
        int nn = idx >> 5, kp = idx & 31;
        __nv_bfloat162 v = __halves2bfloat162(t[2 * kp][nn], t[2 * kp + 1][nn]);
        *reinterpret_cast<__nv_bfloat162*>(g_Wt + (size_t)(n0 + nn) * K + k0 + 2 * kp) = v;
    }
}

// ---------------- 3) main GEMM (dual path) ----------------
// Both paths: BM=128 x BN=256 x BK=64, 4-stage cp.async, SW128 128B-row tiles.
__global__ void __launch_bounds__(256, 1) k_gemm(
    const float* __restrict__ bias,
    const float* __restrict__ lb,      // lora_b [8][N]
    float* __restrict__ out) {
    using namespace cfg;
    extern __shared__ __align__(1024) char smem[];
    const uint32_t sbase = smem_u32(smem);
    const int tid  = threadIdx.x;
    const int warp = tid >> 5, lane = tid & 31;
    const int bm0 = blockIdx.y * BM;
    const int bn0 = blockIdx.x * BN;

    auto issue_loads = [&](int kt, int st) {
        {   // A tile [BM][BK] bf16: 128B rows, SW128
            const char* gA = reinterpret_cast<const char*>(
                g_X + (size_t)bm0 * K + (size_t)kt * BK);
            uint32_t s0 = sbase + SMEM_A_OFF + st * A_STAGE;
#pragma unroll
            for (int i = 0; i < 4; i++) {
                int c = tid + i * 256;
                int row = c >> 3, col = c & 7;
                cp_async16(s0 + sw128(row * 128 + col * 16),
                           gA + (size_t)row * (K * 2) + col * 16);
            }
        }
        {   // B tile [BN][BK] bf16 (K-major): 128B rows, SW128
            const char* gB = reinterpret_cast<const char*>(
                g_Wt + (size_t)bn0 * K + (size_t)kt * BK);
            uint32_t s0 = sbase + SMEM_B_OFF + st * B_STAGE;
#pragma unroll
            for (int i = 0; i < 8; i++) {
                int c = tid + i * 256;
                int row = c >> 3, col = c & 7;
                cp_async16(s0 + sw128(row * 128 + col * 16),
                           gB + (size_t)row * (K * 2) + col * 16);
            }
        }
    };

#if HAS_TC
    // ================= tcgen05 path =================
    if (warp == 0) {
        asm volatile("tcgen05.alloc.cta_group::1.sync.aligned.shared::cta.b32 [%0], %1;"
                     :: "r"(sbase), "r"(256u) : "memory");
    }
    if (tid == 0) {
#pragma unroll
        for (int s = 0; s < STAGES; s++) mbar_init(sbase + MBAR_OFF + s * 8, 1);
    }
    __syncthreads();
    uint32_t tmem_base;
    asm volatile("ld.shared.b32 %0, [%1];" : "=r"(tmem_base) : "r"(sbase));

    issue_loads(0, 0); cp_commit();
    issue_loads(1, 1); cp_commit();
    issue_loads(2, 2); cp_commit();

    for (int kt = 0; kt < NK; kt++) {
        const int st = kt & 3;
        cp_wait<2>();
        fence_proxy_async_cta();
        __syncthreads();

        if (tid < 32 && elect_one()) {
            uint64_t ad = make_desc(sbase + SMEM_A_OFF + st * A_STAGE);
            uint64_t bd = make_desc(sbase + SMEM_B_OFF + st * B_STAGE);
#pragma unroll
            for (int ks = 0; ks < 4; ks++)
                mma_f16_ss(tmem_base, ad + ks * 2, bd + ks * 2, IDESC,
                           (kt > 0 || ks > 0) ? 1u : 0u);
            tc_commit(sbase + MBAR_OFF + st * 8);
        }

        const int kn = kt + 3;
        if (kn < NK) {
            const int sn = kn & 3;
            const int u  = kn >> 2;
            if (u >= 1) mbar_wait(sbase + MBAR_OFF + sn * 8, (u - 1) & 1);
            issue_loads(kn, sn);
        }
        cp_commit();
    }

    mbar_wait(sbase + MBAR_OFF + 3 * 8, 1);   // 16th commit on stage 3 = all MMAs done
    tc_fence_after();

    // epilogue: LDTM -> bf16 round + bias + LoRA delta -> smem transpose -> store
    {
        const int rg = warp & 3;
        const int ch = warp >> 2;
        const int m = bm0 + rg * 32 + lane;
        float4 ha = *reinterpret_cast<const float4*>(g_H + m * 8);
        float4 hb = *reinterpret_cast<const float4*>(g_H + m * 8 + 4);
        float h[8] = {ha.x, ha.y, ha.z, ha.w, hb.x, hb.y, hb.z, hb.w};
        float* sc = reinterpret_cast<float*>(smem + 1024) + warp * (32 * 33);

#pragma unroll
        for (int chunk = 0; chunk < 4; chunk++) {
            const int c0 = ch * 128 + chunk * 32;
            uint32_t d[32];
            ldtm_x32(d, tmem_base + c0);
            tc_wait_ld();
            const int n_base = bn0 + c0;
#pragma unroll
            for (int r = 0; r < 32; r++) {
                const int n = n_base + r;
                float delta = 0.0f;
#pragma unroll
                for (int rr = 0; rr < 8; rr++) delta += h[rr] * lb[rr * N + n];
                __nv_bfloat16 bsum = __hadd(__float2bfloat16(__uint_as_float(d[r])),
                                            __float2bfloat16(bias[n]));
                sc[lane * 33 + r] = __bfloat162float(bsum) + 2.0f * delta;
            }
            __syncwarp();
#pragma unroll
            for (int r = 0; r < 32; r++) {
                out[(size_t)(bm0 + rg * 32 + r) * N + n_base + lane] = sc[r * 33 + lane];
            }
            __syncwarp();
        }
    }
    tc_fence_before();
    __syncthreads();
    if (warp == 0) {
        asm volatile("tcgen05.dealloc.cta_group::1.sync.aligned.b32 %0, %1;"
                     :: "r"(tmem_base), "r"(256u));
    }

#else
    // ================= mma.sync fallback path =================
    const int wm = warp >> 2;          // 0..1  (64 rows)
    const int wn = warp & 3;           // 0..3  (64 cols)

    float acc[4][8][4];
#pragma unroll
    for (int i = 0; i < 4; i++)
#pragma unroll
        for (int j = 0; j < 8; j++)
#pragma unroll
            for (int e = 0; e < 4; e++) acc[i][j][e] = 0.0f;

    issue_loads(0, 0); cp_commit();
    issue_loads(1, 1); cp_commit();
    issue_loads(2, 2); cp_commit();

    for (int kt = 0; kt < NK; kt++) {
        const int st = kt & 3;
        cp_wait<2>();
        __syncthreads();
        // prefetch next stage first so DMA overlaps math
        const int kn = kt + 3;
        if (kn < NK) issue_loads(kn, kn & 3);
        cp_commit();

        const uint32_t aST = sbase + SMEM_A_OFF + st * A_STAGE;
        const uint32_t bST = sbase + SMEM_B_OFF + st * B_STAGE;
#pragma unroll
        for (int ks = 0; ks < 4; ks++) {
            uint32_t afrag[4][4], bfrag[4][4];
#pragma unroll
            for (int mt = 0; mt < 4; mt++) {
                int row = wm * 64 + mt * 16 + (lane & 15);
                ldsm_x4(afrag[mt], aST + sw128(row * 128 + ks * 32 + (lane >> 4) * 16));
            }
#pragma unroll
            for (int nt = 0; nt < 4; nt++) {
                int row = wn * 64 + nt * 16 + (lane & 15);
                ldsm_x4(bfrag[nt], bST + sw128(row * 128 + ks * 32 + (lane >> 4) * 16));
            }
#pragma unroll
            for (int mt = 0; mt < 4; mt++)
#pragma unroll
                for (int nt = 0; nt < 4; nt++) {
                    mma16816(acc[mt][2 * nt],     afrag[mt], bfrag[nt][0], bfrag[nt][2]);
                    mma16816(acc[mt][2 * nt + 1], afrag[mt], bfrag[nt][1], bfrag[nt][3]);
                }
        }
    }

    // epilogue: bf16 round, bf16 bias add, fp32 + LoRA delta
    const int mrow = lane >> 2;
    const int ncol = (lane & 3) * 2;
#pragma unroll
    for (int mt = 0; mt < 4; mt++) {
        int m0 = bm0 + wm * 64 + mt * 16 + mrow;
        const float4* h0p = reinterpret_cast<const float4*>(g_H + m0 * 8);
        const float4* h1p = reinterpret_cast<const float4*>(g_H + (m0 + 8) * 8);
        float4 h0a = h0p[0], h0b = h0p[1];
        float4 h1a = h1p[0], h1b = h1p[1];
        float h0r[8] = {h0a.x, h0a.y, h0a.z, h0a.w, h0b.x, h0b.y, h0b.z, h0b.w};
        float h1r[8] = {h1a.x, h1a.y, h1a.z, h1a.w, h1b.x, h1b.y, h1b.z, h1b.w};
#pragma unroll
        for (int nt = 0; nt < 8; nt++) {
            int n0 = bn0 + wn * 64 + nt * 8 + ncol;
            float d00 = 0.f, d01 = 0.f, d10 = 0.f, d11 = 0.f;
#pragma unroll
            for (int r = 0; r < 8; r++) {
                float l0 = lb[r * N + n0];
                float l1 = lb[r * N + n0 + 1];
                d00 += h0r[r] * l0;  d01 += h0r[r] * l1;
                d10 += h1r[r] * l0;  d11 += h1r[r] * l1;
            }
            __nv_bfloat16 bb0 = __float2bfloat16(bias[n0]);
            __nv_bfloat16 bb1 = __float2bfloat16(bias[n0 + 1]);
            float o00 = __bfloat162float(__hadd(__float2bfloat16(acc[mt][nt][0]), bb0)) + 2.0f * d00;
            float o01 = __bfloat162float(__hadd(__float2bfloat16(acc[mt][nt][1]), bb1)) + 2.0f * d01;
            float o10 = __bfloat162float(__hadd(__float2bfloat16(acc[mt][nt][2]), bb0)) + 2.0f * d10;
            float o11 = __bfloat162float(__hadd(__float2bfloat16(acc[mt][nt][3]), bb1)) + 2.0f * d11;
            *reinterpret_cast<float2*>(out + (size_t)m0 * N + n0)       = make_float2(o00, o01);
            *reinterpret_cast<float2*>(out + (size_t)(m0 + 8) * N + n0) = make_float2(o10, o11);
        }
    }
#endif
}

// ---------------- launch ----------------
extern "C" void kernel_launch(void* const* d_in, const int* in_sizes, int n_in,
                              void* d_out, int out_size) {
    using namespace cfg;
    const float* x = nullptr; const void* q = nullptr; const float* scale = nullptr;
    const float* bias = nullptr; const float* la = nullptr; const float* lb = nullptr;
    for (int i = 0; i < n_in; i++) {
        switch (in_sizes[i]) {
            case 33554432: x = (const float*)d_in[i]; break;        // 8192*4096
            case 16777216: q = d_in[i]; break;                      // 4096*4096
            case 135168:   scale = (const float*)d_in[i]; break;    // 33*4096
            case 4096:     bias = (const float*)d_in[i]; break;
            case 32768:                                             // lora_a then lora_b
                if (!la) la = (const float*)d_in[i];
                else     lb = (const float*)d_in[i];
                break;
            default: break;
        }
    }
    float* out = (float*)d_out;

    k_detect<<<1, 256>>>((const unsigned*)q);
    k_dequant_t<<<dim3(N / 64, K / 64), 256>>>((const int*)q, scale);
    k_lora_conv<<<M / 32, 128>>>(x, la);

    cudaFuncSetAttribute(k_gemm, cudaFuncAttributeMaxDynamicSharedMemorySize, SMEM_TOTAL);
    k_gemm<<<dim3(N / BN, M / BM), 256, SMEM_TOTAL>>>(bias, lb, out);
}